// round 11
// baseline (speedup 1.0000x reference)
#include <cuda_runtime.h>
#include <stdint.h>

#define D 128
#define MAX_N (1 << 18)
#define RPB 128        // REDG edges per block (warps 0-3, 32 each)
#define TPB 128        // TMA edges per block  (warps 4-7, 32 each)
#define TEB 4          // TMA rows per staging buffer

__device__ int   g_cnt[MAX_N];
__device__ float g_inv[MAX_N];

// ---------------------------------------------------------------------------
// K0: zero counts
// ---------------------------------------------------------------------------
__global__ void zero_cnt_kernel(int N) {
    int i = blockIdx.x * blockDim.x + threadIdx.x;
    if (i < N) g_cnt[i] = 0;
}

// ---------------------------------------------------------------------------
// K1: histogram of segment ids, 4 edges/thread (vectorized, streaming loads)
// ---------------------------------------------------------------------------
__global__ void hist_kernel(const int* __restrict__ index, long long E) {
    long long base = ((long long)blockIdx.x * blockDim.x + threadIdx.x) * 4;
    if (base >= E) return;
    if (base + 4 <= E) {
        int4 v = __ldcs((const int4*)(index + base));
        atomicAdd(&g_cnt[v.x], 1);
        atomicAdd(&g_cnt[v.y], 1);
        atomicAdd(&g_cnt[v.z], 1);
        atomicAdd(&g_cnt[v.w], 1);
    } else {
        for (long long e = base; e < E; e++)
            atomicAdd(&g_cnt[__ldg(&index[e])], 1);
    }
}

// ---------------------------------------------------------------------------
// K2: zero output + compute reciprocal counts
// ---------------------------------------------------------------------------
__global__ void prep_kernel(float4* __restrict__ out4, long long n4, int N) {
    long long i = (long long)blockIdx.x * blockDim.x + threadIdx.x;
    long long stride = (long long)gridDim.x * blockDim.x;
    for (long long k = i; k < n4; k += stride)
        out4[k] = make_float4(0.f, 0.f, 0.f, 0.f);
    for (long long k = i; k < N; k += stride) {
        int c = g_cnt[k];
        g_inv[k] = 1.0f / (float)max(c, 1);
    }
}

// ---------------------------------------------------------------------------
// K3: hybrid scatter-mean.
//     warps 0-3: red.global.v4 (LSU pipe)      edges [0, Ea)
//     warps 4-7: cp.reduce.async.bulk (TMA)    edges [Ea, E)
//     Inputs streamed (evict-first); RED/bulk dst hinted evict-last so the
//     51 MB output working set stays L2-resident. Contributions pre-scaled.
// ---------------------------------------------------------------------------
__global__ __launch_bounds__(256) void hybrid_kernel(
        const float4* __restrict__ msg4,
        const int* __restrict__ index,
        float* __restrict__ out,
        long long Ea, long long E) {
    __shared__ float4 sbuf[4][2][TEB][D / 4];   // 16 KB staging for TMA warps

    int warp = threadIdx.x >> 5;
    int lane = threadIdx.x & 31;

    uint64_t pol;
    asm("createpolicy.fractional.L2::evict_last.b64 %0, 1.0;" : "=l"(pol));

    if (warp < 4) {
        // ---------------- REDG path ----------------
        long long base = (long long)blockIdx.x * RPB + (long long)warp * 32;
#pragma unroll
        for (int b = 0; b < 8; b++) {
            long long e0 = base + b * 4;
            if (e0 >= Ea) break;
            int nb = (int)min(4LL, Ea - e0);

            int seg = 0; float inv = 0.f;
            if (lane < nb) {
                seg = __ldcs(&index[e0 + lane]);
                inv = g_inv[seg];
            }

            float4 v[4];
#pragma unroll
            for (int e = 0; e < 4; e++)
                if (e < nb) v[e] = __ldcs(&msg4[(e0 + e) * (D / 4) + lane]);

#pragma unroll
            for (int e = 0; e < 4; e++) {
                if (e >= nb) break;
                int   segE = __shfl_sync(0xffffffffu, seg, e);
                float invE = __shfl_sync(0xffffffffu, inv, e);
                float4 w = v[e];
                w.x *= invE; w.y *= invE; w.z *= invE; w.w *= invE;
                float* dst = out + (long long)segE * D + lane * 4;
                asm volatile(
                    "red.global.add.L2::cache_hint.v4.f32 [%0], {%1,%2,%3,%4}, %5;"
                    :: "l"(dst), "f"(w.x), "f"(w.y), "f"(w.z), "f"(w.w), "l"(pol)
                    : "memory");
            }
        }
    } else {
        // ---------------- TMA bulk-reduce path ----------------
        int tw = warp - 4;
        long long base = Ea + (long long)blockIdx.x * TPB + (long long)tw * 32;
        if (base >= E) return;

        int cur = 0;
#pragma unroll
        for (int b = 0; b < 8; b++) {
            long long e0 = base + b * TEB;
            if (e0 >= E) break;
            int nb = (int)min((long long)TEB, E - e0);

            int seg = 0; float inv = 0.f;
            if (lane < nb) {
                seg = __ldcs(&index[e0 + lane]);
                inv = g_inv[seg];
            }

#pragma unroll
            for (int e = 0; e < TEB; e++) {
                if (e >= nb) break;
                float invE = __shfl_sync(0xffffffffu, inv, e);
                float4 v = __ldcs(&msg4[(e0 + e) * (D / 4) + lane]);
                v.x *= invE; v.y *= invE; v.z *= invE; v.w *= invE;
                sbuf[tw][cur][e][lane] = v;
            }
            __syncwarp();

            if (lane < nb) {
                asm volatile("fence.proxy.async.shared::cta;" ::: "memory");
                uint32_t src = (uint32_t)__cvta_generic_to_shared(
                                   &sbuf[tw][cur][lane][0]);
                float* dst = out + (long long)seg * D;
                asm volatile(
                    "cp.reduce.async.bulk.global.shared::cta.bulk_group.add"
                    ".L2::cache_hint.f32 [%0], [%1], %2, %3;"
                    :: "l"(dst), "r"(src), "n"(D * 4), "l"(pol) : "memory");
                asm volatile("cp.async.bulk.commit_group;" ::: "memory");
            }

            cur ^= 1;
            if (lane < TEB)
                asm volatile("cp.async.bulk.wait_group 1;" ::: "memory");
            __syncwarp();
        }
        if (lane < TEB)
            asm volatile("cp.async.bulk.wait_group 0;" ::: "memory");
    }
}

// ---------------------------------------------------------------------------
extern "C" void kernel_launch(void* const* d_in, const int* in_sizes, int n_in,
                              void* d_out, int out_size) {
    const float4* msg4  = (const float4*)d_in[0];
    const int*    index = (const int*)d_in[1];
    // d_in[2] (t) unused by the reference
    float* out = (float*)d_out;

    long long E = in_sizes[1];
    int N = out_size / D;
    long long n4 = (long long)out_size / 4;

    long long Ea = (E / 2) & ~3LL;   // 50/50 LSU : TMA split

    zero_cnt_kernel<<<(N + 255) / 256, 256>>>(N);
    hist_kernel<<<(int)((E + 1023) / 1024), 256>>>(index, E);
    prep_kernel<<<2048, 256>>>((float4*)out, n4, N);
    {
        long long ba = (Ea + RPB - 1) / RPB;
        long long bg = (E - Ea + TPB - 1) / TPB;
        int grid = (int)(ba > bg ? ba : bg);
        hybrid_kernel<<<grid, 256>>>(msg4, index, out, Ea, E);
    }
}

// round 12
// speedup vs baseline: 1.2423x; 1.2423x over previous
#include <cuda_runtime.h>
#include <stdint.h>

#define D 128
#define MAX_N (1 << 18)

__device__ int   g_cnt[MAX_N];
__device__ float g_inv[MAX_N];

// ---------------------------------------------------------------------------
// K0: zero counts
// ---------------------------------------------------------------------------
__global__ void zero_cnt_kernel(int N) {
    int i = blockIdx.x * blockDim.x + threadIdx.x;
    if (i < N) g_cnt[i] = 0;
}

// ---------------------------------------------------------------------------
// K1: histogram of segment ids, 4 edges/thread (vectorized, streaming loads)
// ---------------------------------------------------------------------------
__global__ void hist_kernel(const int* __restrict__ index, long long E) {
    long long base = ((long long)blockIdx.x * blockDim.x + threadIdx.x) * 4;
    if (base >= E) return;
    if (base + 4 <= E) {
        int4 v = __ldcs((const int4*)(index + base));
        atomicAdd(&g_cnt[v.x], 1);
        atomicAdd(&g_cnt[v.y], 1);
        atomicAdd(&g_cnt[v.z], 1);
        atomicAdd(&g_cnt[v.w], 1);
    } else {
        for (long long e = base; e < E; e++)
            atomicAdd(&g_cnt[__ldg(&index[e])], 1);
    }
}

// ---------------------------------------------------------------------------
// K2: zero output + compute reciprocal counts
// ---------------------------------------------------------------------------
__global__ void prep_kernel(float4* __restrict__ out4, long long n4, int N) {
    long long i = (long long)blockIdx.x * blockDim.x + threadIdx.x;
    long long stride = (long long)gridDim.x * blockDim.x;
    for (long long k = i; k < n4; k += stride)
        out4[k] = make_float4(0.f, 0.f, 0.f, 0.f);
    for (long long k = i; k < N; k += stride) {
        int c = g_cnt[k];
        g_inv[k] = 1.0f / (float)max(c, 1);
    }
}

// ---------------------------------------------------------------------------
// K3: scatter-mean. 4 edges per warp; msg/index streamed (evict-first),
//     RED destination hinted evict-last so the 51 MB output working set
//     stays pinned in L2 while the 1 GB stream passes through.
//     Contributions pre-scaled by 1/count -> output is the final mean.
// ---------------------------------------------------------------------------
__global__ __launch_bounds__(256) void scatter_kernel(
        const float4* __restrict__ msg4,
        const int* __restrict__ index,
        float* __restrict__ out,
        long long E) {
    long long warp_id = ((long long)blockIdx.x * blockDim.x + threadIdx.x) >> 5;
    int lane = threadIdx.x & 31;
    long long base = warp_id * 4;
    if (base >= E) return;
    int nb = (int)min(4LL, E - base);

    uint64_t pol;
    asm("createpolicy.fractional.L2::evict_last.b64 %0, 1.0;" : "=l"(pol));

    // lanes 0..3: coalesced index load + reciprocal lookup
    int seg = 0;
    float inv = 0.f;
    if (lane < nb) {
        seg = __ldcs(&index[base + lane]);
        inv = g_inv[seg];
    }

    // front-batch the 4 independent row loads — streaming, evict-first
    float4 v[4];
#pragma unroll
    for (int e = 0; e < 4; e++)
        if (e < nb) v[e] = __ldcs(&msg4[(base + e) * (D / 4) + lane]);

#pragma unroll
    for (int e = 0; e < 4; e++) {
        if (e >= nb) break;
        int   segE = __shfl_sync(0xffffffffu, seg, e);
        float invE = __shfl_sync(0xffffffffu, inv, e);
        float4 w = v[e];
        w.x *= invE; w.y *= invE; w.z *= invE; w.w *= invE;
        float* dst = out + (long long)segE * D + lane * 4;
        asm volatile(
            "red.global.add.L2::cache_hint.v4.f32 [%0], {%1,%2,%3,%4}, %5;"
            :: "l"(dst), "f"(w.x), "f"(w.y), "f"(w.z), "f"(w.w), "l"(pol)
            : "memory");
    }
}

// ---------------------------------------------------------------------------
extern "C" void kernel_launch(void* const* d_in, const int* in_sizes, int n_in,
                              void* d_out, int out_size) {
    const float4* msg4  = (const float4*)d_in[0];
    const int*    index = (const int*)d_in[1];
    // d_in[2] (t) unused by the reference
    float* out = (float*)d_out;

    long long E = in_sizes[1];
    int N = out_size / D;
    long long n4 = (long long)out_size / 4;

    zero_cnt_kernel<<<(N + 255) / 256, 256>>>(N);
    hist_kernel<<<(int)((E + 1023) / 1024), 256>>>(index, E);
    prep_kernel<<<2048, 256>>>((float4*)out, n4, N);
    {
        long long warps = (E + 3) / 4;
        long long threads = warps * 32;
        int blocks = (int)((threads + 255) / 256);
        scatter_kernel<<<blocks, 256>>>(msg4, index, out, E);
    }
}

// round 13
// speedup vs baseline: 1.2437x; 1.0011x over previous
#include <cuda_runtime.h>
#include <stdint.h>

#define D 128
#define MAX_N (1 << 18)

__device__ int   g_cnt[MAX_N];
__device__ float g_inv[MAX_N];

// ---------------------------------------------------------------------------
// K0: zero counts
// ---------------------------------------------------------------------------
__global__ void zero_cnt_kernel(int N) {
    int i = blockIdx.x * blockDim.x + threadIdx.x;
    if (i < N) g_cnt[i] = 0;
}

// ---------------------------------------------------------------------------
// K1: histogram of segment ids, 4 edges/thread (vectorized, streaming loads)
// ---------------------------------------------------------------------------
__global__ void hist_kernel(const int* __restrict__ index, long long E) {
    long long base = ((long long)blockIdx.x * blockDim.x + threadIdx.x) * 4;
    if (base >= E) return;
    if (base + 4 <= E) {
        int4 v = __ldcs((const int4*)(index + base));
        atomicAdd(&g_cnt[v.x], 1);
        atomicAdd(&g_cnt[v.y], 1);
        atomicAdd(&g_cnt[v.z], 1);
        atomicAdd(&g_cnt[v.w], 1);
    } else {
        for (long long e = base; e < E; e++)
            atomicAdd(&g_cnt[__ldg(&index[e])], 1);
    }
}

// ---------------------------------------------------------------------------
// K2: zero output + compute reciprocal counts
// ---------------------------------------------------------------------------
__global__ void prep_kernel(float4* __restrict__ out4, long long n4, int N) {
    long long i = (long long)blockIdx.x * blockDim.x + threadIdx.x;
    long long stride = (long long)gridDim.x * blockDim.x;
    for (long long k = i; k < n4; k += stride)
        out4[k] = make_float4(0.f, 0.f, 0.f, 0.f);
    for (long long k = i; k < N; k += stride) {
        int c = g_cnt[k];
        g_inv[k] = 1.0f / (float)max(c, 1);
    }
}

// ---------------------------------------------------------------------------
// K3: scatter-mean. 4 edges per warp; msg/index streamed (evict-first),
//     RED destination hinted evict-last so the 51 MB output working set
//     stays pinned in L2 while the 1 GB stream passes through.
//     Contributions pre-scaled by 1/count -> output is the final mean.
// ---------------------------------------------------------------------------
__global__ __launch_bounds__(256) void scatter_kernel(
        const float4* __restrict__ msg4,
        const int* __restrict__ index,
        float* __restrict__ out,
        long long E) {
    long long warp_id = ((long long)blockIdx.x * blockDim.x + threadIdx.x) >> 5;
    int lane = threadIdx.x & 31;
    long long base = warp_id * 4;
    if (base >= E) return;
    int nb = (int)min(4LL, E - base);

    uint64_t pol;
    asm("createpolicy.fractional.L2::evict_last.b64 %0, 1.0;" : "=l"(pol));

    // lanes 0..3: coalesced index load + reciprocal lookup
    int seg = 0;
    float inv = 0.f;
    if (lane < nb) {
        seg = __ldcs(&index[base + lane]);
        inv = g_inv[seg];
    }

    // front-batch the 4 independent row loads — streaming, evict-first
    float4 v[4];
#pragma unroll
    for (int e = 0; e < 4; e++)
        if (e < nb) v[e] = __ldcs(&msg4[(base + e) * (D / 4) + lane]);

#pragma unroll
    for (int e = 0; e < 4; e++) {
        if (e >= nb) break;
        int   segE = __shfl_sync(0xffffffffu, seg, e);
        float invE = __shfl_sync(0xffffffffu, inv, e);
        float4 w = v[e];
        w.x *= invE; w.y *= invE; w.z *= invE; w.w *= invE;
        float* dst = out + (long long)segE * D + lane * 4;
        asm volatile(
            "red.global.add.L2::cache_hint.v4.f32 [%0], {%1,%2,%3,%4}, %5;"
            :: "l"(dst), "f"(w.x), "f"(w.y), "f"(w.z), "f"(w.w), "l"(pol)
            : "memory");
    }
}

// ---------------------------------------------------------------------------
extern "C" void kernel_launch(void* const* d_in, const int* in_sizes, int n_in,
                              void* d_out, int out_size) {
    const float4* msg4  = (const float4*)d_in[0];
    const int*    index = (const int*)d_in[1];
    // d_in[2] (t) unused by the reference
    float* out = (float*)d_out;

    long long E = in_sizes[1];
    int N = out_size / D;
    long long n4 = (long long)out_size / 4;

    zero_cnt_kernel<<<(N + 255) / 256, 256>>>(N);
    hist_kernel<<<(int)((E + 1023) / 1024), 256>>>(index, E);
    prep_kernel<<<2048, 256>>>((float4*)out, n4, N);
    {
        long long warps = (E + 3) / 4;
        long long threads = warps * 32;
        int blocks = (int)((threads + 255) / 256);
        scatter_kernel<<<blocks, 256>>>(msg4, index, out, E);
    }
}